// round 1
// baseline (speedup 1.0000x reference)
#include <cuda_runtime.h>
#include <math.h>

// Problem shapes (fixed for this dataset)
#define G_MAX 20000
#define N_MAX 1024

// ---- device scratch (static: no allocations allowed) ----
__device__ float  g_r[G_MAX];     // 1/softplus(phi)
__device__ float  g_Cg[G_MAX];    // r*log(r) - lgamma(r)
__device__ float  g_tab[512];     // lgamma(k+1)
__device__ float  g_Z[N_MAX];     // sum_g exp(lu)
__device__ float  g_S[N_MAX];     // sum_g Y
__device__ float  g_W[N_MAX];     // log(S) - log(Z)
__device__ double g_acc;          // global log-posterior accumulator

// 0.5*log(2*pi*s^2) with s=2  -> 0.5*log(8*pi)
#define NORM_CONST 1.6120857137646180f
// 0.5*log(2*pi)
#define HALF_LOG_2PI 0.9189385332046727f

// ---- fast lgamma for x > 0.2 (Stirling + shift) ----
__device__ __forceinline__ float lg_pos(float x) {
    float extra = 0.f;
    if (x < 8.f) {
        float p = x * (x + 1.f) * (x + 2.f) * (x + 3.f);
        p *= (x + 4.f) * (x + 5.f) * (x + 6.f) * (x + 7.f);
        extra = -__logf(p);
        x += 8.f;
    }
    float z  = __fdividef(1.f, x);
    float zz = z * z;
    // 1/(12x) - 1/(360x^3) + 1/(1260x^5)
    float ser = z * fmaf(zz, fmaf(zz, 7.9365079365e-4f, -2.7777777778e-3f),
                         8.3333333333e-2f);
    return fmaf(x - 0.5f, __logf(x), ser + extra) - x + HALF_LOG_2PI;
}

// ---------------- k0: zero accumulators ----------------
__global__ void k_zero(int N) {
    int i = blockIdx.x * blockDim.x + threadIdx.x;
    if (i < N) { g_Z[i] = 0.f; g_S[i] = 0.f; }
    if (i == 0) g_acc = 0.0;
}

// ---------------- k1: per-gene setup + priors ----------------
__global__ void k_setup(const float* __restrict__ mu,
                        const float* __restrict__ beta,
                        const float* __restrict__ phi,
                        int G) {
    int i = blockIdx.x * blockDim.x + threadIdx.x;
    double local = 0.0;
    if (i < 4 * G) {                       // beta normal prior
        float b = beta[i];
        local += (double)(-NORM_CONST - 0.125f * b * b);
    }
    if (i < G) {
        float ph = phi[i];
        float sp = fmaxf(ph, 0.f) + log1pf(expf(-fabsf(ph)));  // softplus
        float r  = 1.f / sp;
        g_r[i]  = r;
        g_Cg[i] = r * logf(r) - lgammaf(r);
        float m = mu[i];
        // mu normal prior + gamma(2,1) prior on softplus(phi): log(sp) - sp
        local += (double)(logf(sp) - sp - NORM_CONST - 0.125f * m * m);
    }
    if (i < 512) g_tab[i] = lgammaf((float)i + 1.f);

    // warp-reduce the prior contribution into g_acc
    #pragma unroll
    for (int off = 16; off; off >>= 1)
        local += __shfl_down_sync(0xffffffffu, local, off);
    if ((threadIdx.x & 31) == 0 && local != 0.0)
        atomicAdd(&g_acc, local);
}

// ---------------- k2: per-row sumexp(lu) and sum(Y) ----------------
// grid: (ceil(G/2048), N/8), block: 256 (8 warps; warp w owns row blockIdx.y*8+w)
__global__ void __launch_bounds__(256) k_pass1(
        const float* __restrict__ X, const float* __restrict__ Y,
        const float* __restrict__ mu, const float* __restrict__ beta,
        int N, int G) {
    __shared__ float smu[2048], sb0[2048], sb1[2048], sb2[2048], sb3[2048];
    int gbase = blockIdx.x * 2048;
    for (int idx = threadIdx.x; idx < 2048; idx += 256) {
        int g = gbase + idx;
        bool v = g < G;
        smu[idx] = v ? mu[g]           : -1e30f;
        sb0[idx] = v ? beta[g]         : 0.f;
        sb1[idx] = v ? beta[G + g]     : 0.f;
        sb2[idx] = v ? beta[2 * G + g] : 0.f;
        sb3[idx] = v ? beta[3 * G + g] : 0.f;
    }
    __syncthreads();

    int w = threadIdx.x >> 5, lane = threadIdx.x & 31;
    int n = blockIdx.y * 8 + w;
    float4 xr = ((const float4*)X)[n];
    const float* Yrow = Y + (size_t)n * G + gbase;
    int gmax = min(2048, G - gbase);

    float acc_e = 0.f, acc_y = 0.f;
    for (int k = lane; k < 2048; k += 32) {
        float lu = fmaf(xr.x, sb0[k],
                   fmaf(xr.y, sb1[k],
                   fmaf(xr.z, sb2[k],
                   fmaf(xr.w, sb3[k], smu[k]))));
        acc_e += __expf(lu);            // OOB: smu=-1e30 -> 0
        if (k < gmax) acc_y += Yrow[k];
    }
    #pragma unroll
    for (int off = 16; off; off >>= 1) {
        acc_e += __shfl_down_sync(0xffffffffu, acc_e, off);
        acc_y += __shfl_down_sync(0xffffffffu, acc_y, off);
    }
    if (lane == 0) {
        atomicAdd(&g_Z[n], acc_e);
        atomicAdd(&g_S[n], acc_y);
    }
}

// ---------------- k3: w[n] = log(S) - log(Z) ----------------
__global__ void k_w(int N) {
    int n = blockIdx.x * blockDim.x + threadIdx.x;
    if (n < N) g_W[n] = logf(g_S[n]) - logf(g_Z[n]);
}

// ---------------- k4: main NB log-likelihood pass ----------------
// grid: (ceil(G/256), N/128), block: 256. Thread owns 1 gene; loops 128 rows.
__global__ void __launch_bounds__(256) k_pass2(
        const float* __restrict__ X, const float* __restrict__ Y,
        const float* __restrict__ mu, const float* __restrict__ beta,
        int N, int G) {
    __shared__ float4 sX[128];
    __shared__ float  sW[128];
    __shared__ float  sT[512];
    __shared__ double sRed[8];

    int t = threadIdx.x;
    int row0 = blockIdx.y * 128;
    if (t < 128) { sX[t] = ((const float4*)X)[row0 + t]; sW[t] = g_W[row0 + t]; }
    for (int i = t; i < 512; i += 256) sT[i] = g_tab[i];
    __syncthreads();

    int g = blockIdx.x * 256 + t;
    bool valid = g < G;
    float mug = 0.f, b0 = 0.f, b1 = 0.f, b2 = 0.f, b3 = 0.f, r = 1.f, C = 0.f;
    if (valid) {
        mug = mu[g];
        b0 = beta[g]; b1 = beta[G + g]; b2 = beta[2 * G + g]; b3 = beta[3 * G + g];
        r = g_r[g]; C = g_Cg[g];
    }

    double acc = 0.0;
    if (valid) {
        const float* Yp = Y + (size_t)row0 * G + g;
        #pragma unroll 4
        for (int i = 0; i < 128; i++) {
            float4 xr = sX[i];
            float  wn = sW[i];
            float  y  = Yp[(size_t)i * G];
            float lu = fmaf(xr.x, b0,
                       fmaf(xr.y, b1,
                       fmaf(xr.z, b2,
                       fmaf(xr.w, b3, mug))));
            float tt = lu + wn;               // log mean
            float m  = __expf(tt);
            float lg = __logf(r + m);
            float x  = y + r;
            float c  = lg_pos(x) - sT[(int)y] + fmaf(y, tt, -x * lg);
            acc += (double)c;
        }
        acc += 128.0 * (double)C;             // per-gene constant folded once
    }

    // block reduce (double)
    #pragma unroll
    for (int off = 16; off; off >>= 1)
        acc += __shfl_down_sync(0xffffffffu, acc, off);
    if ((t & 31) == 0) sRed[t >> 5] = acc;
    __syncthreads();
    if (t < 8) {
        double v = sRed[t];
        #pragma unroll
        for (int off = 4; off; off >>= 1)
            v += __shfl_down_sync(0x000000ffu, v, off);
        if (t == 0) atomicAdd(&g_acc, v);
    }
}

// ---------------- k5: finalize ----------------
__global__ void k_final(float* out) {
    out[0] = (float)g_acc;
}

extern "C" void kernel_launch(void* const* d_in, const int* in_sizes, int n_in,
                              void* d_out, int out_size) {
    const float* X    = (const float*)d_in[0];
    const float* Y    = (const float*)d_in[1];
    const float* mu   = (const float*)d_in[2];
    const float* beta = (const float*)d_in[3];
    const float* phi  = (const float*)d_in[4];
    float* out = (float*)d_out;

    int G = in_sizes[2];              // 20000
    int N = in_sizes[1] / G;          // 1024

    k_zero<<<(N + 255) / 256, 256>>>(N);

    int setup_threads = 4 * G;        // covers 4G, G, and 512
    k_setup<<<(setup_threads + 255) / 256, 256>>>(mu, beta, phi, G);

    dim3 g1((G + 2047) / 2048, N / 8);
    k_pass1<<<g1, 256>>>(X, Y, mu, beta, N, G);

    k_w<<<(N + 255) / 256, 256>>>(N);

    dim3 g2((G + 255) / 256, N / 128);
    k_pass2<<<g2, 256>>>(X, Y, mu, beta, N, G);

    k_final<<<1, 1>>>(out);
}

// round 4
// speedup vs baseline: 1.2863x; 1.2863x over previous
#include <cuda_runtime.h>
#include <math.h>
#include <stdint.h>

// Fixed dataset shapes: N=1024, P=4, G=20000 (code tolerates N%32==0, P==4, G<=G_MAX)
#define G_MAX 20480
#define N_MAX 1024
#define NC_MAX 16          // max gene chunks of 2048
#define MAX_B2 4096        // max pass2 blocks

// ---- device scratch (static; no allocations) ----
__device__ __align__(16) float g_r[G_MAX];    // 1/softplus(phi)
__device__ __align__(16) float g_Cg[G_MAX];   // r*log r - lgamma(r) - r + 0.5*log(2pi)
__device__ float  g_tab[512];                 // lgamma(k+1)
__device__ float  g_Zp[NC_MAX * N_MAX];       // per-(chunk,row) sum exp(lu)
__device__ float  g_Sp[NC_MAX * N_MAX];       // per-(chunk,row) sum Y
__device__ double g_prior[NC_MAX];            // per-chunk prior partial
__device__ double g_part[MAX_B2];             // per-pass2-block likelihood partial
__device__ unsigned g_ticket;                 // monotone ticket (mod #blocks)

#define NORM_CONST   1.6120857137646180f      // 0.5*log(8*pi), s=2 normal prior
#define HALF_LOG_2PI 0.9189385332046727f

// ---- block reduce for double (256 threads) ----
__device__ __forceinline__ double blk_reduce256(double v, double* sRed) {
    int t = threadIdx.x, lane = t & 31, wid = t >> 5;
    #pragma unroll
    for (int off = 16; off; off >>= 1)
        v += __shfl_down_sync(0xffffffffu, v, off);
    if (lane == 0) sRed[wid] = v;
    __syncthreads();
    if (t < 8) {
        v = sRed[t];
        #pragma unroll
        for (int off = 4; off; off >>= 1)
            v += __shfl_down_sync(0x000000ffu, v, off);
    }
    return v;  // valid in thread 0
}

// ---- per-element NB log-pmf core (constants folded into per-gene C) ----
// c = stir(y+r) + y*(tt-1) - (y+r)*log(r+e^tt) - lgamma(y+1)
__device__ __forceinline__ float nb_elem(float4 xr, float wn, float y,
                                         float b0, float b1, float b2, float b3,
                                         float mug, float r,
                                         const float* __restrict__ sT) {
    float lu = fmaf(xr.x, b0, fmaf(xr.y, b1, fmaf(xr.z, b2, fmaf(xr.w, b3, mug))));
    float tt = lu + wn;                 // log mean
    float m  = __expf(tt);
    float lg = __logf(r + m);
    float x  = y + r;
    float xs = x, extra = 0.f;
    if (xs < 8.f) {                     // shift for Stirling validity (rare lanes)
        float p = xs * (xs + 1.f) * (xs + 2.f) * (xs + 3.f);
        p *= (xs + 4.f) * (xs + 5.f) * (xs + 6.f) * (xs + 7.f);
        extra = -__logf(p);
        xs += 8.f;
    }
    float z    = __fdividef(1.f, xs);
    float stir = fmaf(xs - 0.5f, __logf(xs), fmaf(0.08333333333f, z, extra));
    return stir - sT[(int)y] + fmaf(y, tt - 1.f, -x * lg);
}

// =========================================================================
// Pass 1: per-(chunk,row) sumexp(lu) and sum(Y); by==0 blocks also do the
// per-gene setup (r, C), priors, and the lgamma table.
// grid (NCHUNK, N/32), 256 threads; warp w owns rows by*32 + 4w .. +3
// =========================================================================
template <bool VEC>
__global__ void __launch_bounds__(256) k_pass1(
        const float* __restrict__ X, const float* __restrict__ Y,
        const float* __restrict__ mu, const float* __restrict__ beta,
        const float* __restrict__ phi, int N, int G) {
    __shared__ float smu[2048], sb0[2048], sb1[2048], sb2[2048], sb3[2048];
    __shared__ double sRed[8];

    int gbase = blockIdx.x * 2048;
    int gmax  = min(2048, G - gbase);
    for (int i = threadIdx.x; i < 2048; i += 256) {
        int g = gbase + i;
        bool v = (i < gmax);
        smu[i] = v ? __ldg(mu + g)         : -1e30f;
        sb0[i] = v ? __ldg(beta + g)       : 0.f;
        sb1[i] = v ? __ldg(beta + G + g)   : 0.f;
        sb2[i] = v ? __ldg(beta + 2*G + g) : 0.f;
        sb3[i] = v ? __ldg(beta + 3*G + g) : 0.f;
    }
    __syncthreads();

    int w = threadIdx.x >> 5, lane = threadIdx.x & 31;
    int n0 = blockIdx.y * 32 + w * 4;
    const float4* X4 = (const float4*)X;
    float4 xr[4];
    const float* Yr[4];
    #pragma unroll
    for (int r = 0; r < 4; r++) {
        int n = min(n0 + r, N - 1);
        xr[r] = X4[n];
        Yr[r] = Y + (size_t)n * G + gbase;
    }

    float ae[4] = {0.f, 0.f, 0.f, 0.f};
    float ay[4] = {0.f, 0.f, 0.f, 0.f};

    #pragma unroll 2
    for (int it = 0; it < 16; it++) {
        int j  = it * 32 + lane;     // quad index in chunk
        int g4 = j * 4;
        float4 m4 = ((const float4*)smu)[j];
        float4 a0 = ((const float4*)sb0)[j];
        float4 a1 = ((const float4*)sb1)[j];
        float4 a2 = ((const float4*)sb2)[j];
        float4 a3 = ((const float4*)sb3)[j];
        #pragma unroll
        for (int r = 0; r < 4; r++) {
            float4 y;
            if (g4 + 3 < gmax) {
                if (VEC) y = *(const float4*)(Yr[r] + g4);
                else { y.x = Yr[r][g4]; y.y = Yr[r][g4+1];
                       y.z = Yr[r][g4+2]; y.w = Yr[r][g4+3]; }
            } else {
                y.x = (g4+0 < gmax) ? Yr[r][g4+0] : 0.f;
                y.y = (g4+1 < gmax) ? Yr[r][g4+1] : 0.f;
                y.z = (g4+2 < gmax) ? Yr[r][g4+2] : 0.f;
                y.w = (g4+3 < gmax) ? Yr[r][g4+3] : 0.f;
            }
            float l0 = fmaf(xr[r].x, a0.x, fmaf(xr[r].y, a1.x, fmaf(xr[r].z, a2.x, fmaf(xr[r].w, a3.x, m4.x))));
            float l1 = fmaf(xr[r].x, a0.y, fmaf(xr[r].y, a1.y, fmaf(xr[r].z, a2.y, fmaf(xr[r].w, a3.y, m4.y))));
            float l2 = fmaf(xr[r].x, a0.z, fmaf(xr[r].y, a1.z, fmaf(xr[r].z, a2.z, fmaf(xr[r].w, a3.z, m4.z))));
            float l3 = fmaf(xr[r].x, a0.w, fmaf(xr[r].y, a1.w, fmaf(xr[r].z, a2.w, fmaf(xr[r].w, a3.w, m4.w))));
            ae[r] += (__expf(l0) + __expf(l1)) + (__expf(l2) + __expf(l3));
            ay[r] += (y.x + y.y) + (y.z + y.w);
        }
    }

    #pragma unroll
    for (int r = 0; r < 4; r++) {
        float e = ae[r], s = ay[r];
        #pragma unroll
        for (int off = 16; off; off >>= 1) {
            e += __shfl_down_sync(0xffffffffu, e, off);
            s += __shfl_down_sync(0xffffffffu, s, off);
        }
        if (lane == 0 && n0 + r < N) {
            g_Zp[blockIdx.x * N_MAX + n0 + r] = e;
            g_Sp[blockIdx.x * N_MAX + n0 + r] = s;
        }
    }

    // ---- setup + priors (one row-block per chunk) ----
    if (blockIdx.y == 0) {
        double lp = 0.0;
        for (int i = threadIdx.x; i < gmax; i += 256) {
            int g = gbase + i;
            float ph = __ldg(phi + g);
            float sp = fmaxf(ph, 0.f) + log1pf(expf(-fabsf(ph)));  // softplus
            float r  = 1.f / sp;
            g_r[g]  = r;
            g_Cg[g] = r * logf(r) - lgammaf(r) - r + HALF_LOG_2PI;
            float m  = smu[i];
            float b0 = sb0[i], b1 = sb1[i], b2 = sb2[i], b3 = sb3[i];
            lp += (double)(logf(sp) - sp - NORM_CONST - 0.125f * m * m);
            lp += (double)(-4.f * NORM_CONST
                           - 0.125f * ((b0*b0 + b1*b1) + (b2*b2 + b3*b3)));
        }
        if (blockIdx.x == 0)
            for (int i = threadIdx.x; i < 512; i += 256)
                g_tab[i] = lgammaf((float)i + 1.f);
        __syncthreads();
        double tot = blk_reduce256(lp, sRed);
        if (threadIdx.x == 0) g_prior[blockIdx.x] = tot;
    }
}

// =========================================================================
// Pass 2: main NB likelihood. grid (ceil(G/1024), ceil(N/16)), 256 threads.
// Thread owns 4 genes (float4), loops 16 rows; float accumulation.
// Last block (ticket) folds all partials + priors -> out[0].
// =========================================================================
template <bool VEC>
__global__ void __launch_bounds__(256) k_pass2(
        const float* __restrict__ X, const float* __restrict__ Y,
        const float* __restrict__ mu, const float* __restrict__ beta,
        float* __restrict__ out, int N, int G, int NCHUNK, int nblocks) {
    __shared__ float4 sX[16];
    __shared__ float  sW[16];
    __shared__ float  sT[512];
    __shared__ double sRed[8];
    __shared__ int    sLast;

    int t = threadIdx.x;
    int row0 = blockIdx.y * 16;
    int rh   = min(16, N - row0);
    if (t < 16) {
        int n = min(row0 + t, N - 1);
        sX[t] = ((const float4*)X)[n];
        float Z = 0.f, S = 0.f;
        for (int c = 0; c < NCHUNK; c++) {
            Z += g_Zp[c * N_MAX + n];
            S += g_Sp[c * N_MAX + n];
        }
        sW[t] = __logf(S) - __logf(Z);
    }
    for (int i = t; i < 512; i += 256) sT[i] = g_tab[i];
    __syncthreads();

    int g4 = (blockIdx.x * 256 + t) * 4;
    bool valid = g4 < G;
    float a0 = 0.f, a1 = 0.f, a2 = 0.f, a3 = 0.f;
    double d = 0.0;

    if (valid) {
        bool full = (g4 + 3 < G);
        int gc0 = g4;
        int gc1 = min(g4 + 1, G - 1);
        int gc2 = min(g4 + 2, G - 1);
        int gc3 = min(g4 + 3, G - 1);
        // per-gene parameters (clamped scalar loads; once per thread)
        float m0 = __ldg(mu+gc0), m1 = __ldg(mu+gc1), m2 = __ldg(mu+gc2), m3 = __ldg(mu+gc3);
        float p00 = __ldg(beta+gc0),       p01 = __ldg(beta+gc1),       p02 = __ldg(beta+gc2),       p03 = __ldg(beta+gc3);
        float p10 = __ldg(beta+G+gc0),     p11 = __ldg(beta+G+gc1),     p12 = __ldg(beta+G+gc2),     p13 = __ldg(beta+G+gc3);
        float p20 = __ldg(beta+2*G+gc0),   p21 = __ldg(beta+2*G+gc1),   p22 = __ldg(beta+2*G+gc2),   p23 = __ldg(beta+2*G+gc3);
        float p30 = __ldg(beta+3*G+gc0),   p31 = __ldg(beta+3*G+gc1),   p32 = __ldg(beta+3*G+gc2),   p33 = __ldg(beta+3*G+gc3);
        float r0 = g_r[gc0], r1 = g_r[gc1], r2 = g_r[gc2], r3 = g_r[gc3];
        float C0 = g_Cg[gc0], C1 = g_Cg[gc1], C2 = g_Cg[gc2], C3 = g_Cg[gc3];

        #pragma unroll 2
        for (int i = 0; i < rh; i++) {
            const float* Yp = Y + (size_t)(row0 + i) * G;
            float4 y;
            if (full && VEC) {
                y = *(const float4*)(Yp + g4);
            } else {
                y.x = Yp[gc0]; y.y = Yp[gc1]; y.z = Yp[gc2]; y.w = Yp[gc3];
            }
            float4 xr = sX[i];
            float  wn = sW[i];
            a0 += nb_elem(xr, wn, y.x, p00, p10, p20, p30, m0, r0, sT);
            a1 += nb_elem(xr, wn, y.y, p01, p11, p21, p31, m1, r1, sT);
            a2 += nb_elem(xr, wn, y.z, p02, p12, p22, p32, m2, r2, sT);
            a3 += nb_elem(xr, wn, y.w, p03, p13, p23, p33, m3, r3, sT);
        }
        double rhd = (double)rh;
        d += (double)a0 + rhd * (double)C0;
        if (g4 + 1 < G) d += (double)a1 + rhd * (double)C1;
        if (g4 + 2 < G) d += (double)a2 + rhd * (double)C2;
        if (g4 + 3 < G) d += (double)a3 + rhd * (double)C3;
    }

    double bsum = blk_reduce256(d, sRed);
    int bid = blockIdx.y * gridDim.x + blockIdx.x;
    if (t == 0) {
        g_part[bid] = bsum;
        __threadfence();
        unsigned old = atomicAdd(&g_ticket, 1u);
        sLast = ((old % (unsigned)nblocks) == (unsigned)(nblocks - 1));
    }
    __syncthreads();

    if (sLast) {
        double s = 0.0;
        for (int i = t; i < nblocks; i += 256) s += g_part[i];
        if (t < NCHUNK) s += g_prior[t];
        __syncthreads();
        double tot = blk_reduce256(s, sRed);
        if (t == 0) out[0] = (float)tot;
    }
}

extern "C" void kernel_launch(void* const* d_in, const int* in_sizes, int n_in,
                              void* d_out, int out_size) {
    const float* X    = (const float*)d_in[0];
    const float* Y    = (const float*)d_in[1];
    const float* mu   = (const float*)d_in[2];
    const float* beta = (const float*)d_in[3];
    const float* phi  = (const float*)d_in[4];
    float* out = (float*)d_out;

    int G = in_sizes[2];          // 20000
    int N = in_sizes[1] / G;      // 1024

    int NCHUNK = (G + 2047) / 2048;
    bool vec = ((G & 3) == 0) && ((((unsigned long long)Y) & 15ull) == 0ull);

    dim3 g1(NCHUNK, (N + 31) / 32);
    if (vec) k_pass1<true><<<g1, 256>>>(X, Y, mu, beta, phi, N, G);
    else     k_pass1<false><<<g1, 256>>>(X, Y, mu, beta, phi, N, G);

    int gx2 = (G + 1023) / 1024;
    int gy2 = (N + 15) / 16;
    int nb  = gx2 * gy2;          // 1280 <= MAX_B2
    dim3 g2(gx2, gy2);
    if (vec) k_pass2<true><<<g2, 256>>>(X, Y, mu, beta, out, N, G, NCHUNK, nb);
    else     k_pass2<false><<<g2, 256>>>(X, Y, mu, beta, out, N, G, NCHUNK, nb);
}

// round 5
// speedup vs baseline: 1.5491x; 1.2043x over previous
#include <cuda_runtime.h>
#include <math.h>
#include <stdint.h>

// Fixed dataset shapes: N=1024, P=4, G=20000 (tolerates N%32==0, P==4, G<=G_MAX)
#define G_MAX 20480
#define N_MAX 1024
#define CH    1024         // genes per pass1 chunk
#define NC_MAX 32          // max gene chunks
#define MAX_B2 4096        // max pass2 blocks

// ---- device scratch (static; no allocations) ----
__device__ __align__(16) float g_r[G_MAX];    // 1/softplus(phi)
__device__ __align__(16) float g_Cg[G_MAX];   // r*log r - lgamma(r) - r + 0.5*log(2pi)
__device__ float  g_tab[512];                 // lgamma(k+1) + k
__device__ float  g_Zp[NC_MAX * N_MAX];       // per-(chunk,row) sum exp(lu)
__device__ float  g_Sp[NC_MAX * N_MAX];       // per-(chunk,row) sum Y
__device__ double g_prior[NC_MAX];            // per-chunk prior partial
__device__ double g_part[MAX_B2];             // per-pass2-block likelihood partial
__device__ unsigned g_ticket;                 // monotone ticket (mod #blocks)

#define NORM_CONST   1.6120857137646180f      // 0.5*log(8*pi), s=2 normal prior
#define HALF_LOG_2PI 0.9189385332046727f

// ---- block reduce for double (256 threads) ----
__device__ __forceinline__ double blk_reduce256(double v, double* sRed) {
    int t = threadIdx.x, lane = t & 31, wid = t >> 5;
    #pragma unroll
    for (int off = 16; off; off >>= 1)
        v += __shfl_down_sync(0xffffffffu, v, off);
    if (lane == 0) sRed[wid] = v;
    __syncthreads();
    if (t < 8) {
        v = sRed[t];
        #pragma unroll
        for (int off = 4; off; off >>= 1)
            v += __shfl_down_sync(0x000000ffu, v, off);
    }
    return v;  // valid in thread 0
}

// ---- per-element NB log-pmf core ----
// contributes: stirling(lgamma(y+r)) - [lgamma(y+1)+y] + y*tt - (y+r)*log(r+m)
// (the -r + 0.5*log(2pi) pieces live in the per-gene constant C)
__device__ __forceinline__ float nb_elem(float4 xr, float wn, float y,
                                         float b0, float b1, float b2, float b3,
                                         float mug, float r,
                                         const float* __restrict__ sT) {
    float lu = fmaf(xr.x, b0, fmaf(xr.y, b1, fmaf(xr.z, b2, fmaf(xr.w, b3, mug))));
    float tt = lu + wn;                 // log mean
    float m  = __expf(tt);
    float lg = __logf(r + m);
    float x  = y + r;
    float xs = x, extra = 0.f;
    if (xs < 8.f) {                     // shift for Stirling validity (rare lanes)
        float p = xs * (xs + 1.f) * (xs + 2.f) * (xs + 3.f);
        p *= (xs + 4.f) * (xs + 5.f) * (xs + 6.f) * (xs + 7.f);
        extra = -__logf(p) - 8.f;       // -8: Stirling's -x uses SHIFTED x (bug fix)
        xs += 8.f;
    }
    float z  = __fdividef(1.f, xs);
    float zz = z * z;
    float ser = z * fmaf(zz, -2.7777778e-3f, 8.3333333e-2f);   // 1/12x - 1/360x^3
    float stir = fmaf(xs - 0.5f, __logf(xs), ser + extra);
    return stir - sT[(int)y] + fmaf(y, tt, -x * lg);
}

// =========================================================================
// Pass 1: per-(chunk,row) sumexp(lu) and sum(Y); by==0 blocks also do the
// per-gene setup (r, C), priors, and the lgamma table.
// grid (NCHUNK, N/32), 256 threads; warp w owns rows by*32 + 4w .. +3
// =========================================================================
template <bool VEC>
__global__ void __launch_bounds__(256) k_pass1(
        const float* __restrict__ X, const float* __restrict__ Y,
        const float* __restrict__ mu, const float* __restrict__ beta,
        const float* __restrict__ phi, int N, int G) {
    __shared__ float smu[CH], sb0[CH], sb1[CH], sb2[CH], sb3[CH];
    __shared__ double sRed[8];

    int gbase = blockIdx.x * CH;
    int gmax  = min(CH, G - gbase);
    for (int i = threadIdx.x; i < CH; i += 256) {
        int g = gbase + i;
        bool v = (i < gmax);
        smu[i] = v ? __ldg(mu + g)         : -1e30f;
        sb0[i] = v ? __ldg(beta + g)       : 0.f;
        sb1[i] = v ? __ldg(beta + G + g)   : 0.f;
        sb2[i] = v ? __ldg(beta + 2*G + g) : 0.f;
        sb3[i] = v ? __ldg(beta + 3*G + g) : 0.f;
    }
    __syncthreads();

    int w = threadIdx.x >> 5, lane = threadIdx.x & 31;
    int n0 = blockIdx.y * 32 + w * 4;
    const float4* X4 = (const float4*)X;
    float4 xr[4];
    const float* Yr[4];
    #pragma unroll
    for (int r = 0; r < 4; r++) {
        int n = min(n0 + r, N - 1);
        xr[r] = X4[n];
        Yr[r] = Y + (size_t)n * G + gbase;
    }

    float ae[4] = {0.f, 0.f, 0.f, 0.f};
    float ay[4] = {0.f, 0.f, 0.f, 0.f};

    #pragma unroll 2
    for (int it = 0; it < CH / 128; it++) {
        int j  = it * 32 + lane;     // quad index in chunk
        int g4 = j * 4;
        float4 m4 = ((const float4*)smu)[j];
        float4 a0 = ((const float4*)sb0)[j];
        float4 a1 = ((const float4*)sb1)[j];
        float4 a2 = ((const float4*)sb2)[j];
        float4 a3 = ((const float4*)sb3)[j];
        #pragma unroll
        for (int r = 0; r < 4; r++) {
            float4 y;
            if (g4 + 3 < gmax) {
                if (VEC) y = *(const float4*)(Yr[r] + g4);
                else { y.x = Yr[r][g4]; y.y = Yr[r][g4+1];
                       y.z = Yr[r][g4+2]; y.w = Yr[r][g4+3]; }
            } else {
                y.x = (g4+0 < gmax) ? Yr[r][g4+0] : 0.f;
                y.y = (g4+1 < gmax) ? Yr[r][g4+1] : 0.f;
                y.z = (g4+2 < gmax) ? Yr[r][g4+2] : 0.f;
                y.w = (g4+3 < gmax) ? Yr[r][g4+3] : 0.f;
            }
            float l0 = fmaf(xr[r].x, a0.x, fmaf(xr[r].y, a1.x, fmaf(xr[r].z, a2.x, fmaf(xr[r].w, a3.x, m4.x))));
            float l1 = fmaf(xr[r].x, a0.y, fmaf(xr[r].y, a1.y, fmaf(xr[r].z, a2.y, fmaf(xr[r].w, a3.y, m4.y))));
            float l2 = fmaf(xr[r].x, a0.z, fmaf(xr[r].y, a1.z, fmaf(xr[r].z, a2.z, fmaf(xr[r].w, a3.z, m4.z))));
            float l3 = fmaf(xr[r].x, a0.w, fmaf(xr[r].y, a1.w, fmaf(xr[r].z, a2.w, fmaf(xr[r].w, a3.w, m4.w))));
            ae[r] += (__expf(l0) + __expf(l1)) + (__expf(l2) + __expf(l3));
            ay[r] += (y.x + y.y) + (y.z + y.w);
        }
    }

    #pragma unroll
    for (int r = 0; r < 4; r++) {
        float e = ae[r], s = ay[r];
        #pragma unroll
        for (int off = 16; off; off >>= 1) {
            e += __shfl_down_sync(0xffffffffu, e, off);
            s += __shfl_down_sync(0xffffffffu, s, off);
        }
        if (lane == 0 && n0 + r < N) {
            g_Zp[blockIdx.x * N_MAX + n0 + r] = e;
            g_Sp[blockIdx.x * N_MAX + n0 + r] = s;
        }
    }

    // ---- setup + priors (one row-block per chunk) ----
    if (blockIdx.y == 0) {
        double lp = 0.0;
        for (int i = threadIdx.x; i < gmax; i += 256) {
            int g = gbase + i;
            float ph = __ldg(phi + g);
            float sp = fmaxf(ph, 0.f) + log1pf(expf(-fabsf(ph)));  // softplus
            float r  = 1.f / sp;
            g_r[g]  = r;
            g_Cg[g] = r * logf(r) - lgammaf(r) - r + HALF_LOG_2PI;
            float m  = smu[i];
            float b0 = sb0[i], b1 = sb1[i], b2 = sb2[i], b3 = sb3[i];
            lp += (double)(logf(sp) - sp - NORM_CONST - 0.125f * m * m);
            lp += (double)(-4.f * NORM_CONST
                           - 0.125f * ((b0*b0 + b1*b1) + (b2*b2 + b3*b3)));
        }
        if (blockIdx.x == 0)
            for (int i = threadIdx.x; i < 512; i += 256)
                g_tab[i] = lgammaf((float)i + 1.f) + (float)i;   // lgamma(y+1)+y
        __syncthreads();
        double tot = blk_reduce256(lp, sRed);
        if (threadIdx.x == 0) g_prior[blockIdx.x] = tot;
    }
}

// =========================================================================
// Pass 2: main NB likelihood. grid (ceil(G/1024), ceil(N/16)), 256 threads.
// Thread owns 4 genes (float4), loops 16 rows; float accumulation.
// Last block (ticket) folds all partials + priors -> out[0].
// =========================================================================
template <bool VEC>
__global__ void __launch_bounds__(256, 4) k_pass2(
        const float* __restrict__ X, const float* __restrict__ Y,
        const float* __restrict__ mu, const float* __restrict__ beta,
        float* __restrict__ out, int N, int G, int NCHUNK, int nblocks) {
    __shared__ float4 sX[16];
    __shared__ float  sW[16];
    __shared__ float  sT[512];
    __shared__ double sRed[8];
    __shared__ int    sLast;

    int t = threadIdx.x;
    int row0 = blockIdx.y * 16;
    int rh   = min(16, N - row0);
    if (t < 16) {
        int n = min(row0 + t, N - 1);
        sX[t] = ((const float4*)X)[n];
        float Z = 0.f, S = 0.f;
        for (int c = 0; c < NCHUNK; c++) {
            Z += g_Zp[c * N_MAX + n];
            S += g_Sp[c * N_MAX + n];
        }
        sW[t] = __logf(S) - __logf(Z);
    }
    for (int i = t; i < 512; i += 256) sT[i] = g_tab[i];
    __syncthreads();

    int g4 = (blockIdx.x * 256 + t) * 4;
    bool valid = g4 < G;
    float a0 = 0.f, a1 = 0.f, a2 = 0.f, a3 = 0.f;
    double d = 0.0;

    if (valid) {
        bool full = (g4 + 3 < G);
        int gc0 = g4;
        int gc1 = min(g4 + 1, G - 1);
        int gc2 = min(g4 + 2, G - 1);
        int gc3 = min(g4 + 3, G - 1);
        float m0 = __ldg(mu+gc0), m1 = __ldg(mu+gc1), m2 = __ldg(mu+gc2), m3 = __ldg(mu+gc3);
        float p00 = __ldg(beta+gc0),       p01 = __ldg(beta+gc1),       p02 = __ldg(beta+gc2),       p03 = __ldg(beta+gc3);
        float p10 = __ldg(beta+G+gc0),     p11 = __ldg(beta+G+gc1),     p12 = __ldg(beta+G+gc2),     p13 = __ldg(beta+G+gc3);
        float p20 = __ldg(beta+2*G+gc0),   p21 = __ldg(beta+2*G+gc1),   p22 = __ldg(beta+2*G+gc2),   p23 = __ldg(beta+2*G+gc3);
        float p30 = __ldg(beta+3*G+gc0),   p31 = __ldg(beta+3*G+gc1),   p32 = __ldg(beta+3*G+gc2),   p33 = __ldg(beta+3*G+gc3);
        float r0 = g_r[gc0], r1 = g_r[gc1], r2 = g_r[gc2], r3 = g_r[gc3];

        // fold per-gene constants up front (frees the C registers for the loop)
        {
            double rhd = (double)rh;
            d += rhd * (double)g_Cg[gc0];
            if (g4 + 1 < G) d += rhd * (double)g_Cg[gc1];
            if (g4 + 2 < G) d += rhd * (double)g_Cg[gc2];
            if (g4 + 3 < G) d += rhd * (double)g_Cg[gc3];
        }

        #pragma unroll 2
        for (int i = 0; i < rh; i++) {
            const float* Yp = Y + (size_t)(row0 + i) * G;
            float4 y;
            if (full && VEC) {
                y = *(const float4*)(Yp + g4);
            } else {
                y.x = Yp[gc0]; y.y = Yp[gc1]; y.z = Yp[gc2]; y.w = Yp[gc3];
            }
            float4 xr = sX[i];
            float  wn = sW[i];
            a0 += nb_elem(xr, wn, y.x, p00, p10, p20, p30, m0, r0, sT);
            a1 += nb_elem(xr, wn, y.y, p01, p11, p21, p31, m1, r1, sT);
            a2 += nb_elem(xr, wn, y.z, p02, p12, p22, p32, m2, r2, sT);
            a3 += nb_elem(xr, wn, y.w, p03, p13, p23, p33, m3, r3, sT);
        }
        d += (double)a0;
        if (g4 + 1 < G) d += (double)a1;
        if (g4 + 2 < G) d += (double)a2;
        if (g4 + 3 < G) d += (double)a3;
    }

    double bsum = blk_reduce256(d, sRed);
    int bid = blockIdx.y * gridDim.x + blockIdx.x;
    if (t == 0) {
        g_part[bid] = bsum;
        __threadfence();
        unsigned old = atomicAdd(&g_ticket, 1u);
        sLast = ((old % (unsigned)nblocks) == (unsigned)(nblocks - 1));
    }
    __syncthreads();

    if (sLast) {
        double s = 0.0;
        for (int i = t; i < nblocks; i += 256) s += g_part[i];
        if (t < NCHUNK) s += g_prior[t];
        __syncthreads();
        double tot = blk_reduce256(s, sRed);
        if (t == 0) out[0] = (float)tot;
    }
}

extern "C" void kernel_launch(void* const* d_in, const int* in_sizes, int n_in,
                              void* d_out, int out_size) {
    const float* X    = (const float*)d_in[0];
    const float* Y    = (const float*)d_in[1];
    const float* mu   = (const float*)d_in[2];
    const float* beta = (const float*)d_in[3];
    const float* phi  = (const float*)d_in[4];
    float* out = (float*)d_out;

    int G = in_sizes[2];          // 20000
    int N = in_sizes[1] / G;      // 1024

    int NCHUNK = (G + CH - 1) / CH;
    bool vec = ((G & 3) == 0) && ((((unsigned long long)Y) & 15ull) == 0ull);

    dim3 g1(NCHUNK, (N + 31) / 32);
    if (vec) k_pass1<true><<<g1, 256>>>(X, Y, mu, beta, phi, N, G);
    else     k_pass1<false><<<g1, 256>>>(X, Y, mu, beta, phi, N, G);

    int gx2 = (G + 1023) / 1024;
    int gy2 = (N + 15) / 16;
    int nb  = gx2 * gy2;          // 1280 <= MAX_B2
    dim3 g2(gx2, gy2);
    if (vec) k_pass2<true><<<g2, 256>>>(X, Y, mu, beta, out, N, G, NCHUNK, nb);
    else     k_pass2<false><<<g2, 256>>>(X, Y, mu, beta, out, N, G, NCHUNK, nb);
}

// round 6
// speedup vs baseline: 2.0531x; 1.3253x over previous
#include <cuda_runtime.h>
#include <math.h>
#include <stdint.h>

// Fixed dataset shapes: N=1024, P=4, G=20000 (tolerates N%32==0, P==4, G<=G_MAX)
#define G_MAX 20480
#define N_MAX 1024
#define CH    512          // genes per pass1 chunk
#define NC_MAX 48          // max gene chunks
#define MAX_B2 4096        // max pass2 blocks

// ---- device scratch (static; no allocations) ----
__device__ __align__(16) float g_r[G_MAX];     // 1/softplus(phi)  (raw)
__device__ __align__(16) float g_C2[G_MAX];    // per-gene const, base-2 units
__device__ __align__(16) float g_mu2[G_MAX];   // mu * log2e
__device__ __align__(16) float g_q0[G_MAX];    // beta row 0 * log2e
__device__ __align__(16) float g_q1[G_MAX];
__device__ __align__(16) float g_q2[G_MAX];
__device__ __align__(16) float g_q3[G_MAX];
__device__ float  g_tab[512];                  // (lgamma(k+1)+k) * log2e
__device__ float  g_Zp[NC_MAX * N_MAX];        // per-(chunk,row) sum exp(lu)
__device__ float  g_Sp[NC_MAX * N_MAX];        // per-(chunk,row) sum Y
__device__ double g_prior[NC_MAX];             // per-chunk prior partial (nats)
__device__ double g_part[MAX_B2];              // per-pass2-block partial (nats)
__device__ unsigned g_ticket;                  // monotone ticket (mod #blocks)

#define NORM_CONST   1.6120857137646180f       // 0.5*log(8*pi), s=2 normal prior
#define HALF_LOG_2PI 0.9189385332046727f
#define LOG2E        1.4426950408889634f
#define LN2          0.6931471805599453
#define SER_K        0.12022458674074694f      // LOG2E / 12
#define SHIFT4       5.7707801635558537f       // 4 * LOG2E

// raw MUFU ops (1 issue slot each)
__device__ __forceinline__ float ex2a(float a){ float r; asm("ex2.approx.ftz.f32 %0,%1;":"=f"(r):"f"(a)); return r; }
__device__ __forceinline__ float lg2a(float a){ float r; asm("lg2.approx.ftz.f32 %0,%1;":"=f"(r):"f"(a)); return r; }
__device__ __forceinline__ float rcpa(float a){ float r; asm("rcp.approx.ftz.f32 %0,%1;":"=f"(r):"f"(a)); return r; }

// ---- block reduce for double (256 threads) ----
__device__ __forceinline__ double blk_reduce256(double v, double* sRed) {
    int t = threadIdx.x, lane = t & 31, wid = t >> 5;
    #pragma unroll
    for (int off = 16; off; off >>= 1)
        v += __shfl_down_sync(0xffffffffu, v, off);
    if (lane == 0) sRed[wid] = v;
    __syncthreads();
    if (t < 8) {
        v = sRed[t];
        #pragma unroll
        for (int off = 4; off; off >>= 1)
            v += __shfl_down_sync(0x000000ffu, v, off);
    }
    return v;  // valid in thread 0
}

// ---- per-element NB log-pmf core, BASE-2 units ----
// b*, mug are pre-scaled by log2e; wn = log2(S/Z); result must be * ln2 later.
__device__ __forceinline__ float nb_elem(float4 xr, float wn, float y,
                                         float b0, float b1, float b2, float b3,
                                         float mug, float r,
                                         const float* __restrict__ sT) {
    float tt = fmaf(xr.x, b0, fmaf(xr.y, b1, fmaf(xr.z, b2, fmaf(xr.w, b3, mug)))) + wn;
    float m  = ex2a(tt);                 // mean (linear)
    float lg = lg2a(r + m);              // log2(r+m)
    float x  = y + r;
    float xs = x, extra = 0.f;
    if (x < 4.f) {                       // shift-by-4 for Stirling validity
        float p = (x * (x + 1.f)) * ((x + 2.f) * (x + 3.f));
        extra = -lg2a(p) - SHIFT4;       // -4*log2e: Stirling's -x uses shifted x
        xs = x + 4.f;
    }
    float z    = rcpa(xs);
    float stir = fmaf(xs - 0.5f, lg2a(xs), fmaf(z, SER_K, extra));
    return stir - sT[(int)y] + fmaf(y, tt, -x * lg);
}

// =========================================================================
// Pass 1: per-(chunk,row) sumexp(lu) and sum(Y); by==0 blocks also do the
// per-gene setup (r, C2, scaled params), priors, and the lgamma table.
// grid (NCHUNK, N/32), 256 threads; warp w owns rows by*32 + 4w .. +3
// =========================================================================
template <bool VEC>
__global__ void __launch_bounds__(256) k_pass1(
        const float* __restrict__ X, const float* __restrict__ Y,
        const float* __restrict__ mu, const float* __restrict__ beta,
        const float* __restrict__ phi, int N, int G) {
    __shared__ float smu[CH], sb0[CH], sb1[CH], sb2[CH], sb3[CH];
    __shared__ double sRed[8];

    int gbase = blockIdx.x * CH;
    int gmax  = min(CH, G - gbase);
    for (int i = threadIdx.x; i < CH; i += 256) {
        int g = gbase + i;
        bool v = (i < gmax);
        smu[i] = v ? __ldg(mu + g)         * LOG2E : -1e30f;
        sb0[i] = v ? __ldg(beta + g)       * LOG2E : 0.f;
        sb1[i] = v ? __ldg(beta + G + g)   * LOG2E : 0.f;
        sb2[i] = v ? __ldg(beta + 2*G + g) * LOG2E : 0.f;
        sb3[i] = v ? __ldg(beta + 3*G + g) * LOG2E : 0.f;
    }
    __syncthreads();

    int w = threadIdx.x >> 5, lane = threadIdx.x & 31;
    int n0 = blockIdx.y * 32 + w * 4;
    const float4* X4 = (const float4*)X;
    float4 xr[4];
    const float* Yr[4];
    #pragma unroll
    for (int r = 0; r < 4; r++) {
        int n = min(n0 + r, N - 1);
        xr[r] = X4[n];
        Yr[r] = Y + (size_t)n * G + gbase;
    }

    float ae[4] = {0.f, 0.f, 0.f, 0.f};
    float ay[4] = {0.f, 0.f, 0.f, 0.f};

    #pragma unroll 2
    for (int it = 0; it < CH / 128; it++) {
        int j  = it * 32 + lane;     // quad index in chunk
        int g4 = j * 4;
        float4 m4 = ((const float4*)smu)[j];
        float4 a0 = ((const float4*)sb0)[j];
        float4 a1 = ((const float4*)sb1)[j];
        float4 a2 = ((const float4*)sb2)[j];
        float4 a3 = ((const float4*)sb3)[j];
        #pragma unroll
        for (int r = 0; r < 4; r++) {
            float4 y;
            if (g4 + 3 < gmax) {
                if (VEC) y = *(const float4*)(Yr[r] + g4);
                else { y.x = Yr[r][g4]; y.y = Yr[r][g4+1];
                       y.z = Yr[r][g4+2]; y.w = Yr[r][g4+3]; }
            } else {
                y.x = (g4+0 < gmax) ? Yr[r][g4+0] : 0.f;
                y.y = (g4+1 < gmax) ? Yr[r][g4+1] : 0.f;
                y.z = (g4+2 < gmax) ? Yr[r][g4+2] : 0.f;
                y.w = (g4+3 < gmax) ? Yr[r][g4+3] : 0.f;
            }
            float l0 = fmaf(xr[r].x, a0.x, fmaf(xr[r].y, a1.x, fmaf(xr[r].z, a2.x, fmaf(xr[r].w, a3.x, m4.x))));
            float l1 = fmaf(xr[r].x, a0.y, fmaf(xr[r].y, a1.y, fmaf(xr[r].z, a2.y, fmaf(xr[r].w, a3.y, m4.y))));
            float l2 = fmaf(xr[r].x, a0.z, fmaf(xr[r].y, a1.z, fmaf(xr[r].z, a2.z, fmaf(xr[r].w, a3.z, m4.z))));
            float l3 = fmaf(xr[r].x, a0.w, fmaf(xr[r].y, a1.w, fmaf(xr[r].z, a2.w, fmaf(xr[r].w, a3.w, m4.w))));
            ae[r] += (ex2a(l0) + ex2a(l1)) + (ex2a(l2) + ex2a(l3));
            ay[r] += (y.x + y.y) + (y.z + y.w);
        }
    }

    #pragma unroll
    for (int r = 0; r < 4; r++) {
        float e = ae[r], s = ay[r];
        #pragma unroll
        for (int off = 16; off; off >>= 1) {
            e += __shfl_down_sync(0xffffffffu, e, off);
            s += __shfl_down_sync(0xffffffffu, s, off);
        }
        if (lane == 0 && n0 + r < N) {
            g_Zp[blockIdx.x * N_MAX + n0 + r] = e;
            g_Sp[blockIdx.x * N_MAX + n0 + r] = s;
        }
    }

    // ---- setup + priors (one row-block per chunk) ----
    if (blockIdx.y == 0) {
        double lp = 0.0;
        for (int i = threadIdx.x; i < gmax; i += 256) {
            int g = gbase + i;
            float ph = __ldg(phi + g);
            float sp = fmaxf(ph, 0.f) + log1pf(expf(-fabsf(ph)));  // softplus
            float r  = 1.f / sp;
            g_r[g]   = r;
            g_C2[g]  = (r * logf(r) - lgammaf(r) - r + HALF_LOG_2PI) * LOG2E;
            g_mu2[g] = smu[i];            // already * log2e
            g_q0[g]  = sb0[i];
            g_q1[g]  = sb1[i];
            g_q2[g]  = sb2[i];
            g_q3[g]  = sb3[i];
            float m  = __ldg(mu + g);
            float b0 = __ldg(beta + g),       b1 = __ldg(beta + G + g);
            float b2 = __ldg(beta + 2*G + g), b3 = __ldg(beta + 3*G + g);
            lp += (double)(logf(sp) - sp - NORM_CONST - 0.125f * m * m);
            lp += (double)(-4.f * NORM_CONST
                           - 0.125f * ((b0*b0 + b1*b1) + (b2*b2 + b3*b3)));
        }
        if (blockIdx.x == 0)
            for (int i = threadIdx.x; i < 512; i += 256)
                g_tab[i] = (lgammaf((float)i + 1.f) + (float)i) * LOG2E;
        __syncthreads();
        double tot = blk_reduce256(lp, sRed);
        if (threadIdx.x == 0) g_prior[blockIdx.x] = tot;
    }
}

// =========================================================================
// Pass 2: main NB likelihood. grid (ceil(G/1024), ceil(N/16)), 256 threads.
// Thread owns 4 genes (float4), loops 16 rows; base-2 float accumulation,
// *ln2 once per thread. Last block (ticket) folds partials + priors -> out.
// =========================================================================
template <bool VEC>
__global__ void __launch_bounds__(256, 4) k_pass2(
        const float* __restrict__ X, const float* __restrict__ Y,
        float* __restrict__ out, int N, int G, int NCHUNK, int nblocks) {
    __shared__ float4 sX[16];
    __shared__ float  sW[16];
    __shared__ float  sT[512];
    __shared__ double sRed[8];
    __shared__ int    sLast;

    int t = threadIdx.x;
    int row0 = blockIdx.y * 16;
    int rh   = min(16, N - row0);
    if (t < 16) {
        int n = min(row0 + t, N - 1);
        sX[t] = ((const float4*)X)[n];
        float Z = 0.f, S = 0.f;
        for (int c = 0; c < NCHUNK; c++) {
            Z += g_Zp[c * N_MAX + n];
            S += g_Sp[c * N_MAX + n];
        }
        sW[t] = lg2a(S) - lg2a(Z);       // base-2 row offset
    }
    for (int i = t; i < 512; i += 256) sT[i] = g_tab[i];
    __syncthreads();

    int g4 = (blockIdx.x * 256 + t) * 4;
    bool valid = g4 < G;
    float a0 = 0.f, a1 = 0.f, a2 = 0.f, a3 = 0.f;
    double d = 0.0;

    if (valid) {
        bool full = (g4 + 3 < G);
        int gc0 = g4;
        int gc1 = min(g4 + 1, G - 1);
        int gc2 = min(g4 + 2, G - 1);
        int gc3 = min(g4 + 3, G - 1);
        float m0 = g_mu2[gc0], m1 = g_mu2[gc1], m2 = g_mu2[gc2], m3 = g_mu2[gc3];
        float p00 = g_q0[gc0], p01 = g_q0[gc1], p02 = g_q0[gc2], p03 = g_q0[gc3];
        float p10 = g_q1[gc0], p11 = g_q1[gc1], p12 = g_q1[gc2], p13 = g_q1[gc3];
        float p20 = g_q2[gc0], p21 = g_q2[gc1], p22 = g_q2[gc2], p23 = g_q2[gc3];
        float p30 = g_q3[gc0], p31 = g_q3[gc1], p32 = g_q3[gc2], p33 = g_q3[gc3];
        float r0 = g_r[gc0], r1 = g_r[gc1], r2 = g_r[gc2], r3 = g_r[gc3];

        // fold per-gene constants up front (base-2 units)
        {
            float csum = g_C2[gc0];
            if (g4 + 1 < G) csum += g_C2[gc1];
            if (g4 + 2 < G) csum += g_C2[gc2];
            if (g4 + 3 < G) csum += g_C2[gc3];
            d = (double)rh * (double)csum;
        }

        if (full && VEC && rh == 16) {
            const float* Yp = Y + (size_t)row0 * G + g4;
            #pragma unroll 4
            for (int i = 0; i < 16; i++) {
                float4 y = *(const float4*)Yp;
                Yp += G;
                float4 xr = sX[i];
                float  wn = sW[i];
                a0 += nb_elem(xr, wn, y.x, p00, p10, p20, p30, m0, r0, sT);
                a1 += nb_elem(xr, wn, y.y, p01, p11, p21, p31, m1, r1, sT);
                a2 += nb_elem(xr, wn, y.z, p02, p12, p22, p32, m2, r2, sT);
                a3 += nb_elem(xr, wn, y.w, p03, p13, p23, p33, m3, r3, sT);
            }
        } else {
            for (int i = 0; i < rh; i++) {
                const float* Yp = Y + (size_t)(row0 + i) * G;
                float4 y;
                y.x = Yp[gc0]; y.y = Yp[gc1]; y.z = Yp[gc2]; y.w = Yp[gc3];
                float4 xr = sX[i];
                float  wn = sW[i];
                a0 += nb_elem(xr, wn, y.x, p00, p10, p20, p30, m0, r0, sT);
                a1 += nb_elem(xr, wn, y.y, p01, p11, p21, p31, m1, r1, sT);
                a2 += nb_elem(xr, wn, y.z, p02, p12, p22, p32, m2, r2, sT);
                a3 += nb_elem(xr, wn, y.w, p03, p13, p23, p33, m3, r3, sT);
            }
        }
        d += (double)a0;
        if (g4 + 1 < G) d += (double)a1;
        if (g4 + 2 < G) d += (double)a2;
        if (g4 + 3 < G) d += (double)a3;
        d *= LN2;                         // back to nats
    }

    double bsum = blk_reduce256(d, sRed);
    int bid = blockIdx.y * gridDim.x + blockIdx.x;
    if (t == 0) {
        g_part[bid] = bsum;
        __threadfence();
        unsigned old = atomicAdd(&g_ticket, 1u);
        sLast = ((old % (unsigned)nblocks) == (unsigned)(nblocks - 1));
    }
    __syncthreads();

    if (sLast) {
        double s = 0.0;
        for (int i = t; i < nblocks; i += 256) s += g_part[i];
        for (int c = t; c < NCHUNK; c += 256) s += g_prior[c];
        __syncthreads();
        double tot = blk_reduce256(s, sRed);
        if (t == 0) out[0] = (float)tot;
    }
}

extern "C" void kernel_launch(void* const* d_in, const int* in_sizes, int n_in,
                              void* d_out, int out_size) {
    const float* X    = (const float*)d_in[0];
    const float* Y    = (const float*)d_in[1];
    const float* mu   = (const float*)d_in[2];
    const float* beta = (const float*)d_in[3];
    const float* phi  = (const float*)d_in[4];
    float* out = (float*)d_out;

    int G = in_sizes[2];          // 20000
    int N = in_sizes[1] / G;      // 1024

    int NCHUNK = (G + CH - 1) / CH;
    bool vec = ((G & 3) == 0) && ((((unsigned long long)Y) & 15ull) == 0ull);

    dim3 g1(NCHUNK, (N + 31) / 32);
    if (vec) k_pass1<true><<<g1, 256>>>(X, Y, mu, beta, phi, N, G);
    else     k_pass1<false><<<g1, 256>>>(X, Y, mu, beta, phi, N, G);

    int gx2 = (G + 1023) / 1024;
    int gy2 = (N + 15) / 16;
    int nb  = gx2 * gy2;          // 1280 <= MAX_B2
    dim3 g2(gx2, gy2);
    if (vec) k_pass2<true><<<g2, 256>>>(X, Y, out, N, G, NCHUNK, nb);
    else     k_pass2<false><<<g2, 256>>>(X, Y, out, N, G, NCHUNK, nb);
}